// round 5
// baseline (speedup 1.0000x reference)
#include <cuda_runtime.h>
#include <cuda_fp16.h>
#include <cstdint>

#define NN   50000
#define NE   800000
#define FIN  128
#define FHID 128
#define FOUT 64

// ---------------- scratch (static __device__ -- no allocations) ----------------
// NOTE: g_deg / g_cur are zero on first call (static init) and are reset to zero
// by k_scan on every call, so every kernel_launch invocation sees identical state.
static __device__ int   g_deg[NN];     // in-edge count (no self-loop)
static __device__ int   g_cur[NN];
static __device__ float g_dinv[NN];
static __device__ int   g_rowptr[NN + 1];
static __device__ int   g_col[NE];
static __device__ __align__(16) __half g_h1h[(size_t)NN * FHID];  // dinv*(x@W1)
static __device__ __align__(16) __half g_h2h[(size_t)NN * FHID];  // relu(layer1)
static __device__ __align__(16) __half g_h2p[(size_t)NN * FOUT];  // dinv*(h2@W2)

// ---------------- mma helpers ----------------
__device__ __forceinline__ uint32_t cvta_s(const void* p) {
    return (uint32_t)__cvta_generic_to_shared(p);
}
__device__ __forceinline__ void ldmA(uint32_t& a0, uint32_t& a1, uint32_t& a2,
                                     uint32_t& a3, uint32_t addr) {
    asm volatile("ldmatrix.sync.aligned.m8n8.x4.shared.b16 {%0,%1,%2,%3}, [%4];\n"
                 : "=r"(a0), "=r"(a1), "=r"(a2), "=r"(a3) : "r"(addr));
}
__device__ __forceinline__ void ldmBT(uint32_t& b0, uint32_t& b1, uint32_t& b2,
                                      uint32_t& b3, uint32_t addr) {
    asm volatile("ldmatrix.sync.aligned.m8n8.x4.trans.shared.b16 {%0,%1,%2,%3}, [%4];\n"
                 : "=r"(b0), "=r"(b1), "=r"(b2), "=r"(b3) : "r"(addr));
}
__device__ __forceinline__ void mma16816(float* d, uint32_t a0, uint32_t a1,
                                         uint32_t a2, uint32_t a3,
                                         uint32_t b0, uint32_t b1) {
    asm volatile("mma.sync.aligned.m16n8k16.row.col.f32.f16.f16.f32 "
                 "{%0,%1,%2,%3}, {%4,%5,%6,%7}, {%8,%9}, {%0,%1,%2,%3};\n"
                 : "+f"(d[0]), "+f"(d[1]), "+f"(d[2]), "+f"(d[3])
                 : "r"(a0), "r"(a1), "r"(a2), "r"(a3), "r"(b0), "r"(b1));
}

// ---------------- CSR build ----------------
__global__ void k_count(const int* __restrict__ ei) {
    int e = blockIdx.x * blockDim.x + threadIdx.x;
    const int Q = NE / 4;
    if (e < Q) {
        int d0 = __ldg(&ei[NE + e]);
        int d1 = __ldg(&ei[NE + e + Q]);
        int d2 = __ldg(&ei[NE + e + 2 * Q]);
        int d3 = __ldg(&ei[NE + e + 3 * Q]);
        atomicAdd(&g_deg[d0], 1);
        atomicAdd(&g_deg[d1], 1);
        atomicAdd(&g_deg[d2], 1);
        atomicAdd(&g_deg[d3], 1);
    }
}

// one-block, thread-coarsened scan; also resets deg/cur for the next call.
__global__ void __launch_bounds__(1024) k_scan() {
    const int C = (NN + 1023) / 1024;            // 49
    int t = threadIdx.x;
    int lane = t & 31, wid = t >> 5;
    int start = t * C;

    int s = 0;
    #pragma unroll 4
    for (int j = 0; j < C; j++) {
        int i = start + j;
        if (i < NN) s += g_deg[i];               // in-edges (no self)
    }
    int x = s;
    #pragma unroll
    for (int o = 1; o < 32; o <<= 1) {
        int u = __shfl_up_sync(0xFFFFFFFFu, x, o);
        if (lane >= o) x += u;
    }
    __shared__ int wsum[32];
    if (lane == 31) wsum[wid] = x;
    __syncthreads();
    if (wid == 0) {
        int w = wsum[lane];
        #pragma unroll
        for (int o = 1; o < 32; o <<= 1) {
            int u = __shfl_up_sync(0xFFFFFFFFu, w, o);
            if (lane >= o) w += u;
        }
        wsum[lane] = w;
    }
    __syncthreads();
    int run = x - s + (wid > 0 ? wsum[wid - 1] : 0);
    #pragma unroll 4
    for (int j = 0; j < C; j++) {
        int i = start + j;
        if (i < NN) {
            int d = g_deg[i];
            g_deg[i] = 0;                        // reset for next replay
            g_cur[i] = 0;                        // reset for this call's fill
            g_dinv[i] = rsqrtf((float)(d + 1));  // +1 self-loop
            g_rowptr[i] = run;
            run += d;
        }
    }
    if (t == 1023) g_rowptr[NN] = run;
}

__global__ void k_fill(const int* __restrict__ ei) {
    int e = blockIdx.x * blockDim.x + threadIdx.x;
    const int Q = NE / 4;
    if (e < Q) {
        int d0 = __ldg(&ei[NE + e]);
        int d1 = __ldg(&ei[NE + e + Q]);
        int d2 = __ldg(&ei[NE + e + 2 * Q]);
        int d3 = __ldg(&ei[NE + e + 3 * Q]);
        int s0 = __ldg(&ei[e]);
        int s1 = __ldg(&ei[e + Q]);
        int s2 = __ldg(&ei[e + 2 * Q]);
        int s3 = __ldg(&ei[e + 3 * Q]);
        int p0 = atomicAdd(&g_cur[d0], 1);
        int p1 = atomicAdd(&g_cur[d1], 1);
        int p2 = atomicAdd(&g_cur[d2], 1);
        int p3 = atomicAdd(&g_cur[d3], 1);
        g_col[__ldg(&g_rowptr[d0]) + p0] = s0;
        g_col[__ldg(&g_rowptr[d1]) + p1] = s1;
        g_col[__ldg(&g_rowptr[d2]) + p2] = s2;
        g_col[__ldg(&g_rowptr[d3]) + p3] = s3;
    }
}

// ---------------- GEMM 1 (tensor core): g_h1h = fp16(dinv * (x @ W1)) ----------------
__global__ void __launch_bounds__(256) k_gemm1(const float* __restrict__ X,
                                               const float* __restrict__ W) {
    __shared__ __half As[64][72];     // 64x64 fp16
    __shared__ __half Bs[64][136];    // 64x128 fp16
    int tid = threadIdx.x;
    int row0 = blockIdx.x * 64;
    int wid = tid >> 5, lane = tid & 31;
    int rw = (wid & 3) * 16;
    int cw = (wid >> 2) * 64;
    float acc[8][4] = {};

    #pragma unroll
    for (int kb = 0; kb < 2; kb++) {
        // X tile: 64 rows x 64 cols fp32 -> fp16
        #pragma unroll
        for (int i = 0; i < 4; i++) {
            int idx = tid + i * 256;
            int r = idx >> 4, c4 = idx & 15;
            int row = row0 + r;
            float4 v = (row < NN)
                ? reinterpret_cast<const float4*>(X)[(size_t)row * 32 + kb * 16 + c4]
                : make_float4(0.f, 0.f, 0.f, 0.f);
            *reinterpret_cast<__half2*>(&As[r][c4 * 4])     = __floats2half2_rn(v.x, v.y);
            *reinterpret_cast<__half2*>(&As[r][c4 * 4 + 2]) = __floats2half2_rn(v.z, v.w);
        }
        // W tile: 64 rows x 128 cols fp32 -> fp16 (inline convert)
        #pragma unroll
        for (int i = 0; i < 8; i++) {
            int idx = tid + i * 256;
            int r = idx >> 5, c4 = idx & 31;
            float4 v = reinterpret_cast<const float4*>(W)[(size_t)(kb * 64 + r) * 32 + c4];
            *reinterpret_cast<__half2*>(&Bs[r][c4 * 4])     = __floats2half2_rn(v.x, v.y);
            *reinterpret_cast<__half2*>(&Bs[r][c4 * 4 + 2]) = __floats2half2_rn(v.z, v.w);
        }
        __syncthreads();
        #pragma unroll
        for (int k = 0; k < 4; k++) {
            int k0 = k * 16;
            uint32_t a0, a1, a2, a3;
            ldmA(a0, a1, a2, a3, cvta_s(&As[rw + (lane & 15)][k0 + (lane >> 4) * 8]));
            #pragma unroll
            for (int nn = 0; nn < 8; nn += 2) {
                uint32_t b0, b1, b2, b3;
                ldmBT(b0, b1, b2, b3,
                      cvta_s(&Bs[k0 + (lane & 15)][cw + nn * 8 + (lane >> 4) * 8]));
                mma16816(acc[nn],     a0, a1, a2, a3, b0, b1);
                mma16816(acc[nn + 1], a0, a1, a2, a3, b2, b3);
            }
        }
        __syncthreads();
    }
    int g  = lane >> 2, cq = (lane & 3) * 2;
    int ra = row0 + rw + g, rb = ra + 8;
    float da = (ra < NN) ? g_dinv[ra] : 0.f;
    float db = (rb < NN) ? g_dinv[rb] : 0.f;
    #pragma unroll
    for (int nn = 0; nn < 8; nn++) {
        int col = cw + nn * 8 + cq;
        if (ra < NN)
            *reinterpret_cast<__half2*>(&g_h1h[(size_t)ra * FHID + col]) =
                __floats2half2_rn(acc[nn][0] * da, acc[nn][1] * da);
        if (rb < NN)
            *reinterpret_cast<__half2*>(&g_h1h[(size_t)rb * FHID + col]) =
                __floats2half2_rn(acc[nn][2] * db, acc[nn][3] * db);
    }
}

// ---------------- AGG 1 ----------------
__device__ __forceinline__ void acc_row16(float4& acc, uint2 raw) {
    float2 f01 = __half22float2(*reinterpret_cast<__half2*>(&raw.x));
    float2 f23 = __half22float2(*reinterpret_cast<__half2*>(&raw.y));
    acc.x += f01.x; acc.y += f01.y; acc.z += f23.x; acc.w += f23.y;
}

__global__ void __launch_bounds__(256) k_agg1(const float* __restrict__ b1) {
    int gw   = (blockIdx.x * 256 + threadIdx.x) >> 5;
    int lane = threadIdx.x & 31;
    if (gw >= NN) return;
    const uint2* h = reinterpret_cast<const uint2*>(g_h1h);
    float4 acc = make_float4(0.f, 0.f, 0.f, 0.f);
    acc_row16(acc, h[(size_t)gw * 32 + lane]);          // self-loop

    int s0 = g_rowptr[gw], s1 = g_rowptr[gw + 1];
    int j = s0;
    for (; j + 3 < s1; j += 4) {
        int sA = __ldg(&g_col[j]);
        int sB = __ldg(&g_col[j + 1]);
        int sC = __ldg(&g_col[j + 2]);
        int sD = __ldg(&g_col[j + 3]);
        uint2 a = __ldg(&h[(size_t)sA * 32 + lane]);
        uint2 b = __ldg(&h[(size_t)sB * 32 + lane]);
        uint2 c = __ldg(&h[(size_t)sC * 32 + lane]);
        uint2 d = __ldg(&h[(size_t)sD * 32 + lane]);
        acc_row16(acc, a); acc_row16(acc, b);
        acc_row16(acc, c); acc_row16(acc, d);
    }
    for (; j < s1; j++) {
        int sA = __ldg(&g_col[j]);
        acc_row16(acc, __ldg(&h[(size_t)sA * 32 + lane]));
    }
    float dv = g_dinv[gw];
    float4 bb = reinterpret_cast<const float4*>(b1)[lane];
    float zx = fmaxf(acc.x * dv + bb.x, 0.f);
    float zy = fmaxf(acc.y * dv + bb.y, 0.f);
    float zz = fmaxf(acc.z * dv + bb.z, 0.f);
    float zw = fmaxf(acc.w * dv + bb.w, 0.f);
    uint2 packed;
    __half2 lo = __floats2half2_rn(zx, zy);
    __half2 hi = __floats2half2_rn(zz, zw);
    packed.x = *reinterpret_cast<unsigned*>(&lo);
    packed.y = *reinterpret_cast<unsigned*>(&hi);
    reinterpret_cast<uint2*>(g_h2h)[(size_t)gw * 32 + lane] = packed;
}

// ---------------- GEMM 2 (tensor core): g_h2p = fp16(dinv * (h2 @ W2)) ----------------
__global__ void __launch_bounds__(256) k_gemm2(const float* __restrict__ W) {
    __shared__ __half As[64][72];
    __shared__ __half Bs[64][72];
    int tid = threadIdx.x;
    int row0 = blockIdx.x * 64;
    int wid = tid >> 5, lane = tid & 31;
    int rw = (wid & 3) * 16;
    int cw = (wid >> 2) * 32;
    float acc[4][4] = {};

    #pragma unroll
    for (int kb = 0; kb < 2; kb++) {
        #pragma unroll
        for (int i = 0; i < 4; i++) {
            int idx = tid + i * 256;
            int r = idx >> 4, c = idx & 15;
            int row = row0 + r;
            uint2 v = (row < NN)
                ? reinterpret_cast<const uint2*>(g_h2h + (size_t)row * FHID + kb * 64)[c]
                : make_uint2(0u, 0u);
            *reinterpret_cast<uint2*>(&As[r][c * 4]) = v;
        }
        // W2 tile: 64x64 fp32 -> fp16 inline
        #pragma unroll
        for (int i = 0; i < 4; i++) {
            int idx = tid + i * 256;
            int r = idx >> 4, c4 = idx & 15;
            float4 v = reinterpret_cast<const float4*>(W)[(size_t)(kb * 64 + r) * 16 + c4];
            *reinterpret_cast<__half2*>(&Bs[r][c4 * 4])     = __floats2half2_rn(v.x, v.y);
            *reinterpret_cast<__half2*>(&Bs[r][c4 * 4 + 2]) = __floats2half2_rn(v.z, v.w);
        }
        __syncthreads();
        #pragma unroll
        for (int k = 0; k < 4; k++) {
            int k0 = k * 16;
            uint32_t a0, a1, a2, a3;
            ldmA(a0, a1, a2, a3, cvta_s(&As[rw + (lane & 15)][k0 + (lane >> 4) * 8]));
            #pragma unroll
            for (int nn = 0; nn < 4; nn += 2) {
                uint32_t b0, b1, b2, b3;
                ldmBT(b0, b1, b2, b3,
                      cvta_s(&Bs[k0 + (lane & 15)][cw + nn * 8 + (lane >> 4) * 8]));
                mma16816(acc[nn],     a0, a1, a2, a3, b0, b1);
                mma16816(acc[nn + 1], a0, a1, a2, a3, b2, b3);
            }
        }
        __syncthreads();
    }
    int g  = lane >> 2, cq = (lane & 3) * 2;
    int ra = row0 + rw + g, rb = ra + 8;
    float da = (ra < NN) ? g_dinv[ra] : 0.f;
    float db = (rb < NN) ? g_dinv[rb] : 0.f;
    #pragma unroll
    for (int nn = 0; nn < 4; nn++) {
        int col = cw + nn * 8 + cq;
        if (ra < NN)
            *reinterpret_cast<__half2*>(&g_h2p[(size_t)ra * FOUT + col]) =
                __floats2half2_rn(acc[nn][0] * da, acc[nn][1] * da);
        if (rb < NN)
            *reinterpret_cast<__half2*>(&g_h2p[(size_t)rb * FOUT + col]) =
                __floats2half2_rn(acc[nn][2] * db, acc[nn][3] * db);
    }
}

// ---------------- AGG 2 ----------------
__global__ void __launch_bounds__(256) k_agg2(const float* __restrict__ b2,
                                              float* __restrict__ out) {
    int gw   = (blockIdx.x * 256 + threadIdx.x) >> 5;
    int lane = threadIdx.x & 31;
    if (gw >= NN) return;
    const __half2* h = reinterpret_cast<const __half2*>(g_h2p);
    float2 acc = __half22float2(h[(size_t)gw * 32 + lane]);   // self-loop
    int s0 = g_rowptr[gw], s1 = g_rowptr[gw + 1];
    int j = s0;
    for (; j + 3 < s1; j += 4) {
        int sA = __ldg(&g_col[j]);
        int sB = __ldg(&g_col[j + 1]);
        int sC = __ldg(&g_col[j + 2]);
        int sD = __ldg(&g_col[j + 3]);
        float2 a = __half22float2(__ldg(&h[(size_t)sA * 32 + lane]));
        float2 b = __half22float2(__ldg(&h[(size_t)sB * 32 + lane]));
        float2 c = __half22float2(__ldg(&h[(size_t)sC * 32 + lane]));
        float2 d = __half22float2(__ldg(&h[(size_t)sD * 32 + lane]));
        acc.x += (a.x + b.x) + (c.x + d.x);
        acc.y += (a.y + b.y) + (c.y + d.y);
    }
    for (; j < s1; j++) {
        int sA = __ldg(&g_col[j]);
        float2 a = __half22float2(__ldg(&h[(size_t)sA * 32 + lane]));
        acc.x += a.x; acc.y += a.y;
    }
    float dv = g_dinv[gw];
    float2 bb = reinterpret_cast<const float2*>(b2)[lane];
    float2 z;
    z.x = acc.x * dv + bb.x;
    z.y = acc.y * dv + bb.y;
    reinterpret_cast<float2*>(out)[(size_t)gw * 32 + lane] = z;
}

// ---------------- launch ----------------
extern "C" void kernel_launch(void* const* d_in, const int* in_sizes, int n_in,
                              void* d_out, int out_size) {
    const float* x  = (const float*)d_in[0];
    const int*   ei = (const int*)d_in[1];
    const float* W1 = (const float*)d_in[2];
    const float* b1 = (const float*)d_in[3];
    const float* W2 = (const float*)d_in[4];
    const float* b2 = (const float*)d_in[5];
    float* out = (float*)d_out;

    static cudaStream_t s_side = nullptr;
    static cudaEvent_t  ev_fork = nullptr, ev_join = nullptr;
    if (!s_side) {
        cudaStreamCreateWithFlags(&s_side, cudaStreamNonBlocking);
        cudaEventCreateWithFlags(&ev_fork, cudaEventDisableTiming);
        cudaEventCreateWithFlags(&ev_join, cudaEventDisableTiming);
    }

    k_count<<<(NE / 4 + 255) / 256, 256>>>(ei);
    k_scan <<<1, 1024>>>();

    // fork: fill (L2-atomic bound) runs concurrently with gemm1 (tensor bound);
    // both depend only on k_scan.
    cudaEventRecord(ev_fork, 0);
    cudaStreamWaitEvent(s_side, ev_fork, 0);
    k_fill <<<(NE / 4 + 255) / 256, 256, 0, s_side>>>(ei);
    cudaEventRecord(ev_join, s_side);

    k_gemm1<<<(NN + 63) / 64, 256>>>(x, W1);

    cudaStreamWaitEvent(0, ev_join, 0);
    k_agg1 <<<(NN * 32 + 255) / 256, 256>>>(b1);
    k_gemm2<<<(NN + 63) / 64, 256>>>(W2);
    k_agg2 <<<(NN * 32 + 255) / 256, 256>>>(b2, out);
}